// round 1
// baseline (speedup 1.0000x reference)
#include <cuda_runtime.h>

// Row-normalize: out[row, :] = adj[row, :] * inv(sum(adj[row, :]))
// adj: [L*B*N, N] fp32 with N = 2048. One CTA per row; row held in registers.

static constexpr int ROW_N     = 2048;
static constexpr int THREADS   = 256;
static constexpr int V4_PER_T  = ROW_N / 4 / THREADS;   // 2 float4 per thread

__global__ __launch_bounds__(THREADS)
void normalizer_kernel(const float* __restrict__ adj,
                       float* __restrict__ out)
{
    const long long row  = blockIdx.x;
    const long long base = row * (long long)ROW_N;
    const float4* __restrict__ in4  = reinterpret_cast<const float4*>(adj + base);
    float4* __restrict__       out4 = reinterpret_cast<float4*>(out + base);

    const int t = threadIdx.x;

    // Front-batched vector loads: row lives in registers.
    float4 v[V4_PER_T];
#pragma unroll
    for (int i = 0; i < V4_PER_T; i++)
        v[i] = in4[t + i * THREADS];

    // Per-thread partial sum
    float s = 0.0f;
#pragma unroll
    for (int i = 0; i < V4_PER_T; i++)
        s += (v[i].x + v[i].y) + (v[i].z + v[i].w);

    // Warp reduction
#pragma unroll
    for (int off = 16; off > 0; off >>= 1)
        s += __shfl_xor_sync(0xFFFFFFFFu, s, off);

    // Block reduction across 8 warps
    __shared__ float warp_sums[THREADS / 32];
    __shared__ float inv_shared;
    const int wid = t >> 5;
    const int lid = t & 31;
    if (lid == 0) warp_sums[wid] = s;
    __syncthreads();

    if (t == 0) {
        float deg = 0.0f;
#pragma unroll
        for (int w = 0; w < THREADS / 32; w++)
            deg += warp_sums[w];
        float inv = 1.0f / deg;
        if (!isfinite(inv)) inv = 0.0f;
        inv_shared = inv;
    }
    __syncthreads();

    const float inv = inv_shared;

    // Scale and store
#pragma unroll
    for (int i = 0; i < V4_PER_T; i++) {
        float4 r = v[i];
        r.x *= inv; r.y *= inv; r.z *= inv; r.w *= inv;
        out4[t + i * THREADS] = r;
    }
}

extern "C" void kernel_launch(void* const* d_in, const int* in_sizes, int n_in,
                              void* d_out, int out_size)
{
    const float* adj = (const float*)d_in[0];
    float* out = (float*)d_out;

    const long long total = (long long)in_sizes[0];
    const long long rows  = total / ROW_N;   // 32768 for [2,8,2048,2048]

    normalizer_kernel<<<(unsigned)rows, THREADS>>>(adj, out);
}

// round 3
// speedup vs baseline: 1.0039x; 1.0039x over previous
#include <cuda_runtime.h>

// Row-normalize: out[row, :] = adj[row, :] * inv(sum(adj[row, :]))
// adj: [L*B*N, N] fp32, N = 2048. One CTA per row; row held in registers.
// Streaming (evict-first) hints on both load and store: data is single-use.

static constexpr int ROW_N     = 2048;
static constexpr int THREADS   = 256;
static constexpr int V4_PER_T  = ROW_N / 4 / THREADS;   // 2 float4 per thread
static constexpr int NWARPS    = THREADS / 32;

__global__ __launch_bounds__(THREADS)
void normalizer_kernel(const float* __restrict__ adj,
                       float* __restrict__ out)
{
    const long long row  = blockIdx.x;
    const long long base = row * (long long)ROW_N;
    const float4* __restrict__ in4  = reinterpret_cast<const float4*>(adj + base);
    float4* __restrict__       out4 = reinterpret_cast<float4*>(out + base);

    const int t = threadIdx.x;

    // Front-batched streaming vector loads: row lives in registers.
    float4 v[V4_PER_T];
#pragma unroll
    for (int i = 0; i < V4_PER_T; i++)
        v[i] = __ldcs(&in4[t + i * THREADS]);

    // Per-thread partial sum
    float s = 0.0f;
#pragma unroll
    for (int i = 0; i < V4_PER_T; i++)
        s += (v[i].x + v[i].y) + (v[i].z + v[i].w);

    // Warp reduction
#pragma unroll
    for (int off = 16; off > 0; off >>= 1)
        s += __shfl_xor_sync(0xFFFFFFFFu, s, off);

    // Block reduction: one barrier, every thread folds the 8 warp partials.
    __shared__ float warp_sums[NWARPS];
    if ((t & 31) == 0) warp_sums[t >> 5] = s;
    __syncthreads();

    float deg = 0.0f;
#pragma unroll
    for (int w = 0; w < NWARPS; w++)
        deg += warp_sums[w];

    float inv = 1.0f / deg;
    if (!isfinite(inv)) inv = 0.0f;

    // Scale and streaming store
#pragma unroll
    for (int i = 0; i < V4_PER_T; i++) {
        float4 r = v[i];
        r.x *= inv; r.y *= inv; r.z *= inv; r.w *= inv;
        __stcs(&out4[t + i * THREADS], r);
    }
}

extern "C" void kernel_launch(void* const* d_in, const int* in_sizes, int n_in,
                              void* d_out, int out_size)
{
    const float* adj = (const float*)d_in[0];
    float* out = (float*)d_out;

    const long long total = (long long)in_sizes[0];
    const long long rows  = total / ROW_N;   // 32768 for [2,8,2048,2048]

    normalizer_kernel<<<(unsigned)rows, THREADS>>>(adj, out);
}